// round 9
// baseline (speedup 1.0000x reference)
#include <cuda_runtime.h>
#include <cuda_bf16.h>

// PointGNN, algebraically reduced, single persistent kernel, 1 block/SM:
//   adj(i) = { j : |x_i - x_j|^2 < 0.05 }  (fixed; self always in-set)
//   F_t[j]   = MLP_f([0,0,0,state_j])      (per NODE, not per edge)
//   agg_t[i] = max_{j in adj(i)} F_t[j]    (channelwise; F>=0 so 0-floor exact)
//   state   += relu(MLP_g(agg_t))
// h-MLP provably dead. Neighbor lists built once in SMEM (padded with self to
// x8 -> duplicates harmless under max). g_F double-buffered; 3 grid barriers.
// GRID=128 <= 148 SMs -> exactly one co-resident block per SM: balanced and
// the software grid barrier is deadlock-free.

#define MM    384
#define NODES (4*MM)
#define MASKW 12
#define BN    12
#define TPB   384
#define GRID  (NODES/BN)   // 128
#define MAXD  128

__device__ float    g_Fbuf[2][NODES * 128];
__device__ unsigned g_bar;   // monotonic; wrap-safe barrier

// 8192-float (32KB) cooperative smem staging
__device__ __forceinline__ void stage8k(float* dst, const float* src) {
    const float4* s4 = (const float4*)src;
    float4*       d4 = (float4*)dst;
    for (int idx = threadIdx.x; idx < 2048; idx += TPB) d4[idx] = s4[idx];
}

// grid-wide barrier: monotonic ticket counter, wrap-safe compare
__device__ __forceinline__ void grid_bar() {
    __syncthreads();
    if (threadIdx.x == 0) {
        __threadfence();
        unsigned v = atomicAdd(&g_bar, 1u);
        unsigned target = v - (v % (unsigned)GRID) + (unsigned)GRID;
        unsigned cur;
        do {
            asm volatile("ld.acquire.gpu.u32 %0, [%1];" : "=r"(cur) : "l"(&g_bar));
        } while ((int)(cur - target) < 0);
    }
    __syncthreads();
}

// MLP_f for 12 nodes: sB[i][0..2] = state -> Fout[i*128+c]; sA, sW scratch
__device__ __forceinline__ void f_phase(
    const float* fW1r, float bf1v, float bf2v, float bf3v,
    const float* fW2p, const float* fW3p,
    float (*sA)[128], float (*sB)[128], float* sW,
    float* Fout, int c, int g3c, int k64, int h6)
{
    stage8k(sW, fW2p);                       // latency overlaps layer1
    // layer1: only rows 3..5 of fW1 are live; 6 groups x 2 nodes
    #pragma unroll
    for (int j = 0; j < 2; j++) {
        int i = h6*2 + j;
        float acc = bf1v;
        acc = fmaf(sB[i][0], fW1r[3*64 + k64], acc);
        acc = fmaf(sB[i][1], fW1r[4*64 + k64], acc);
        acc = fmaf(sB[i][2], fW1r[5*64 + k64], acc);
        sA[i][k64] = fmaxf(acc, 0.f);
    }
    __syncthreads();

    // layer2: 64 -> 128, ILP-4 (3 channel groups x 4 nodes)
    float acc2[4];
    #pragma unroll
    for (int j = 0; j < 4; j++) acc2[j] = bf2v;
    #pragma unroll 4
    for (int kk = 0; kk < 64; kk++) {
        float w = sW[kk*128 + c];
        #pragma unroll
        for (int j = 0; j < 4; j++) acc2[j] = fmaf(sA[g3c*4 + j][kk], w, acc2[j]);
    }
    #pragma unroll
    for (int j = 0; j < 4; j++) sB[g3c*4 + j][c] = fmaxf(acc2[j], 0.f);
    __syncthreads();

    // layer3: 128 -> 128 in two 32KB halves, ILP-4
    float acc3[4];
    #pragma unroll
    for (int j = 0; j < 4; j++) acc3[j] = bf3v;

    stage8k(sW, fW3p);
    __syncthreads();
    #pragma unroll 4
    for (int kk = 0; kk < 64; kk++) {
        float w = sW[kk*128 + c];
        #pragma unroll
        for (int j = 0; j < 4; j++) acc3[j] = fmaf(sB[g3c*4 + j][kk], w, acc3[j]);
    }
    __syncthreads();
    stage8k(sW, fW3p + 8192);
    __syncthreads();
    #pragma unroll 4
    for (int kk = 0; kk < 64; kk++) {
        float w = sW[kk*128 + c];
        #pragma unroll
        for (int j = 0; j < 4; j++) acc3[j] = fmaf(sB[g3c*4 + j][64 + kk], w, acc3[j]);
    }
    #pragma unroll
    for (int j = 0; j < 4; j++)
        Fout[(g3c*4 + j)*128 + c] = fmaxf(acc3[j], 0.f);
}

// ---------------------------------------------------------------------------
__global__ __launch_bounds__(TPB) void pointgnn_persistent(
    const float* x, float* state,
    const float* fW1, const float* fb1, const float* fW2, const float* fb2,
    const float* fW3, const float* fb3,
    const float* gW1, const float* gb1, const float* gW2, const float* gb2,
    const float* gW3, const float* gb3)
{
    __shared__ float          sW[8192];
    __shared__ float          sA[BN][128];
    __shared__ float          sB[BN][128];
    __shared__ unsigned short sN[BN][MAXD];
    __shared__ int            sD[BN];
    __shared__ float          sG3[96];

    const int t    = threadIdx.x;
    const int base = blockIdx.x * BN;        // 12 nodes, all in same batch (384%12==0)
    const int n    = base / MM;
    const int c    = t & 127;                // channel lane
    const int g3c  = t >> 7;                 // 0..2 -> node quad
    const int k64  = t & 63;
    const int h6   = t >> 6;                 // 0..5 -> node pair

    // ---- one-time prefetch: all 3 steps' biases + state ----
    float bf1[3], bf2[3], bf3[3], bg1[3], bg2[3], bg3s[3];
    #pragma unroll
    for (int s = 0; s < 3; s++) {
        bf1[s] = fb1[s*64  + k64];
        bf2[s] = fb2[s*128 + c];
        bf3[s] = fb3[s*128 + c];
        bg1[s] = gb1[s*64  + k64];
        bg2[s] = gb2[s*32  + (t & 31)];
    }
    float stv = 0.f;
    if (t < BN*3) {
        stv = x[base*3 + t];
        #pragma unroll
        for (int s = 0; s < 3; s++) bg3s[s] = gb3[s*3 + t % 3];
    }

    // ---- adjacency (once, pure smem): warp-per-node popc compaction ----
    {
        const int warp = t >> 5, lane = t & 31;   // 12 warps = 12 nodes
        const int i = base + warp;
        float xi0 = x[i*3+0], xi1 = x[i*3+1], xi2 = x[i*3+2];
        int cnt = 0;
        #pragma unroll
        for (int wc = 0; wc < MASKW; wc++) {
            int j = wc*32 + lane;
            const float* xj = x + (n*MM + j)*3;
            float dx = xi0 - xj[0], dy = xi1 - xj[1], dz = xi2 - xj[2];
            // non-contracted to match reference's (diff*diff).sum() compare
            float s2 = __fadd_rn(__fadd_rn(__fmul_rn(dx,dx), __fmul_rn(dy,dy)),
                                 __fmul_rn(dz,dz));
            bool pred = s2 < 0.05f;
            unsigned m = __ballot_sync(0xffffffffu, pred);
            int pos = cnt + __popc(m & ((1u << lane) - 1u));
            if (pred && pos < MAXD) sN[warp][pos] = (unsigned short)j;
            cnt += __popc(m);
        }
        if (lane == 0) {
            int cl = cnt < MAXD ? cnt : MAXD;
            int padded = (cl + 7) & ~7;            // pad to x8 for ILP-8 max
            unsigned short self = (unsigned short)(i - n*MM);
            for (int p = cl; p < padded; p++) sN[warp][p] = self;
            sD[warp] = padded;
        }
    }
    if (t < BN*3) sB[t/3][t%3] = stv;              // state := x
    __syncthreads();

    // ---- F0 = MLP_f(x) ----
    f_phase(fW1, bf1[0], bf2[0], bf3[0], fW2, fW3,
            sA, sB, sW, g_Fbuf[0] + base*128, c, g3c, k64, h6);
    grid_bar();

    // ---- 3 timesteps ----
    int cur = 0;
    #pragma unroll
    for (int s = 0; s < 3; s++) {
        stage8k(sW, gW1 + s*8192);                 // overlaps max phase below
        if (t < 96) sG3[t] = gW3[s*96 + t];        // current step's gW3 (384B)

        // phase A: channelwise max over neighbors, 8 loads in flight
        const float* Fn = g_Fbuf[cur] + n*MM*128;
        #pragma unroll
        for (int j = 0; j < 4; j++) {
            int i  = g3c*4 + j;
            int dg = sD[i];
            float m = 0.f;
            for (int d = 0; d < dg; d += 8) {
                float v0 = Fn[sN[i][d+0]*128 + c], v1 = Fn[sN[i][d+1]*128 + c];
                float v2 = Fn[sN[i][d+2]*128 + c], v3 = Fn[sN[i][d+3]*128 + c];
                float v4 = Fn[sN[i][d+4]*128 + c], v5 = Fn[sN[i][d+5]*128 + c];
                float v6 = Fn[sN[i][d+6]*128 + c], v7 = Fn[sN[i][d+7]*128 + c];
                float m01 = fmaxf(v0, v1), m23 = fmaxf(v2, v3);
                float m45 = fmaxf(v4, v5), m67 = fmaxf(v6, v7);
                m = fmaxf(m, fmaxf(fmaxf(m01, m23), fmaxf(m45, m67)));
            }
            sA[i][c] = m;
        }
        __syncthreads();   // also guarantees gW1/sG3 staging complete

        // phase B: g layer1 (128 -> 64), ILP-2, weights in smem
        {
            float a0 = bg1[s], a1 = bg1[s];
            const float* A0 = sA[h6*2], * A1 = sA[h6*2 + 1];
            #pragma unroll 8
            for (int d = 0; d < 128; d++) {
                float w = sW[d*64 + k64];
                a0 = fmaf(A0[d], w, a0);
                a1 = fmaf(A1[d], w, a1);
            }
            sB[h6*2    ][k64] = fmaxf(a0, 0.f);
            sB[h6*2 + 1][k64] = fmaxf(a1, 0.f);
        }
        __syncthreads();

        // phase C: g layer2 (64 -> 32), weights direct from L2 (front-batched)
        {
            int k2 = t & 31, i12 = t >> 5;         // one node per 32-thread group
            const float* W2p = gW2 + s*2048;
            float a = bg2[s];
            #pragma unroll
            for (int d = 0; d < 64; d++) a = fmaf(sB[i12][d], W2p[d*32 + k2], a);
            sA[i12][k2] = fmaxf(a, 0.f);
        }
        __syncthreads();

        // phase D: g layer3 (32 -> 3) + relu + residual (state in regs)
        if (t < BN*3) {
            int i = t / 3, d = t % 3;
            float acc = bg3s[s];
            #pragma unroll
            for (int k3 = 0; k3 < 32; k3++)
                acc = fmaf(sA[i][k3], sG3[k3*3 + d], acc);
            float ns = stv + fmaxf(acc, 0.f);
            stv = ns;
            if (s == 2) state[base*3 + t] = ns;    // final output, once
            else        sB[i][d] = ns;             // feed next f phase
        }
        __syncthreads();

        if (s < 2) {
            f_phase(fW1 + (s+1)*384, bf1[s+1], bf2[s+1], bf3[s+1],
                    fW2 + (s+1)*8192, fW3 + (s+1)*16384,
                    sA, sB, sW, g_Fbuf[cur ^ 1] + base*128, c, g3c, k64, h6);
            grid_bar();
            cur ^= 1;
        }
    }
}

// ---------------------------------------------------------------------------
extern "C" void kernel_launch(void* const* d_in, const int* in_sizes, int n_in,
                              void* d_out, int out_size) {
    const float* x   = (const float*)d_in[0];
    const float* fW1 = (const float*)d_in[7];
    const float* fb1 = (const float*)d_in[8];
    const float* fW2 = (const float*)d_in[9];
    const float* fb2 = (const float*)d_in[10];
    const float* fW3 = (const float*)d_in[11];
    const float* fb3 = (const float*)d_in[12];
    const float* gW1 = (const float*)d_in[13];
    const float* gb1 = (const float*)d_in[14];
    const float* gW2 = (const float*)d_in[15];
    const float* gb2 = (const float*)d_in[16];
    const float* gW3 = (const float*)d_in[17];
    const float* gb3 = (const float*)d_in[18];
    float* state = (float*)d_out;

    pointgnn_persistent<<<GRID, TPB>>>(x, state,
        fW1, fb1, fW2, fb2, fW3, fb3,
        gW1, gb1, gW2, gb2, gW3, gb3);
}

// round 11
// speedup vs baseline: 1.3002x; 1.3002x over previous
#include <cuda_runtime.h>
#include <cuda_bf16.h>

// PointGNN, algebraically reduced, single persistent kernel, 1 block/SM,
// all per-step weights staged into big dynamic smem via cp.async:
//   adj(i) = { j : |x_i - x_j|^2 < 0.05 }  (fixed; self always in-set)
//   F_t[j]   = MLP_f([0,0,0,state_j])      (per NODE, not per edge)
//   agg_t[i] = max_{j in adj(i)} F_t[j]    (channelwise; F>=0 so 0-floor exact)
//   state   += relu(MLP_g(agg_t))
// h-MLP provably dead. Neighbor lists built once in SMEM (padded with self to
// x8). g_F double-buffered; 3 grid barriers. GRID=128 <= 148 SMs -> one
// co-resident block per SM: software grid barrier is deadlock-free.

#define MM    384
#define NODES (4*MM)
#define MASKW 12
#define BN    12
#define TPB   384
#define GRID  (NODES/BN)   // 128
#define MAXD  128

// dynamic smem layout (floats unless noted):
//   sG1 8192 | sG2 2048 | sF2 8192 | sF3 16384 | sA 1536 | sB 1536 | sG3 96
//   | sN 1536 u16 | sD 12 int     => 155,056 bytes
#define SMEM_BYTES 155056

__device__ float    g_Fbuf[2][NODES * 128];
__device__ unsigned g_bar;   // monotonic; wrap-safe barrier

__device__ __forceinline__ void cpa(float* dst, const float* src, int nfloats) {
    for (int idx = threadIdx.x * 4; idx < nfloats; idx += TPB * 4) {
        unsigned sa = (unsigned)__cvta_generic_to_shared(dst + idx);
        asm volatile("cp.async.cg.shared.global [%0], [%1], 16;"
                     :: "r"(sa), "l"(src + idx));
    }
}
__device__ __forceinline__ void cpa_commit() {
    asm volatile("cp.async.commit_group;");
}
template<int N> __device__ __forceinline__ void cpa_wait() {
    asm volatile("cp.async.wait_group %0;" :: "n"(N));
}

// grid-wide barrier: monotonic ticket counter, wrap-safe compare
__device__ __forceinline__ void grid_bar() {
    __syncthreads();
    if (threadIdx.x == 0) {
        __threadfence();
        unsigned v = atomicAdd(&g_bar, 1u);
        unsigned target = v - (v % (unsigned)GRID) + (unsigned)GRID;
        unsigned cur;
        do {
            asm volatile("ld.acquire.gpu.u32 %0, [%1];" : "=r"(cur) : "l"(&g_bar));
        } while ((int)(cur - target) < 0);
    }
    __syncthreads();
}

// ---------------------------------------------------------------------------
__global__ __launch_bounds__(TPB) void pointgnn_persistent(
    const float* x, float* state,
    const float* fW1, const float* fb1, const float* fW2, const float* fb2,
    const float* fW3, const float* fb3,
    const float* gW1, const float* gb1, const float* gW2, const float* gb2,
    const float* gW3, const float* gb3)
{
    extern __shared__ float sm[];
    float*          sG1 = sm;                 // 8192
    float*          sG2 = sG1 + 8192;         // 2048
    float*          sF2 = sG2 + 2048;         // 8192
    float*          sF3 = sF2 + 8192;         // 16384
    float*          sA  = sF3 + 16384;        // 12 x 128
    float*          sB  = sA + 1536;          // 12 x 128
    float*          sG3 = sB + 1536;          // 96
    unsigned short* sN  = (unsigned short*)(sG3 + 96);   // 12 x 128
    int*            sD  = (int*)(sN + BN*MAXD);          // 12

    const int t    = threadIdx.x;
    const int base = blockIdx.x * BN;        // 12 nodes, same batch (384%12==0)
    const int n    = base / MM;
    const int c    = t & 127;                // channel lane
    const int g3c  = t >> 7;                 // 0..2 -> node quad
    const int k64  = t & 63;
    const int h6   = t >> 6;                 // 0..5 -> node pair

    // ---- stage f0 weights immediately (overlap adjacency build) ----
    cpa(sF2, fW2, 8192);  cpa_commit();      // group: F2
    cpa(sF3, fW3, 16384); cpa_commit();      // group: F3

    // ---- one-time prefetch: all 3 steps' biases + state + fW1 rows ----
    float bf1[3], bf2[3], bf3[3], bg1[3], bg2[3], bg3s[3];
    float w1a[3], w1b[3], w1c[3];
    #pragma unroll
    for (int s = 0; s < 3; s++) {
        bf1[s] = fb1[s*64  + k64];
        bf2[s] = fb2[s*128 + c];
        bf3[s] = fb3[s*128 + c];
        bg1[s] = gb1[s*64  + k64];
        bg2[s] = gb2[s*32  + (t & 31)];
        w1a[s] = fW1[s*384 + 3*64 + k64];
        w1b[s] = fW1[s*384 + 4*64 + k64];
        w1c[s] = fW1[s*384 + 5*64 + k64];
    }
    float stv = 0.f;
    if (t < BN*3) {
        stv = x[base*3 + t];
        #pragma unroll
        for (int s = 0; s < 3; s++) bg3s[s] = gb3[s*3 + t % 3];
    }

    // ---- adjacency (once, pure smem): warp-per-node popc compaction ----
    {
        const int warp = t >> 5, lane = t & 31;   // 12 warps = 12 nodes
        const int i = base + warp;
        float xi0 = x[i*3+0], xi1 = x[i*3+1], xi2 = x[i*3+2];
        int cnt = 0;
        #pragma unroll
        for (int wc = 0; wc < MASKW; wc++) {
            int j = wc*32 + lane;
            const float* xj = x + (n*MM + j)*3;
            float dx = xi0 - xj[0], dy = xi1 - xj[1], dz = xi2 - xj[2];
            // non-contracted to match reference's (diff*diff).sum() compare
            float s2 = __fadd_rn(__fadd_rn(__fmul_rn(dx,dx), __fmul_rn(dy,dy)),
                                 __fmul_rn(dz,dz));
            bool pred = s2 < 0.05f;
            unsigned m = __ballot_sync(0xffffffffu, pred);
            int pos = cnt + __popc(m & ((1u << lane) - 1u));
            if (pred && pos < MAXD) sN[warp*MAXD + pos] = (unsigned short)j;
            cnt += __popc(m);
        }
        if (lane == 0) {
            int cl = cnt < MAXD ? cnt : MAXD;
            int padded = (cl + 7) & ~7;            // pad to x8 for ILP-8 max
            unsigned short self = (unsigned short)(i - n*MM);
            for (int p = cl; p < padded; p++) sN[warp*MAXD + p] = self;
            sD[warp] = padded;
        }
    }
    if (t < BN*3) sB[(t/3)*128 + t%3] = stv;       // state := x
    __syncthreads();

    // ================= F0 = MLP_f(x) =================
    {
        // layer1 (rows 3..5 only, weights in regs)
        #pragma unroll
        for (int j = 0; j < 2; j++) {
            int i = h6*2 + j;
            float acc = bf1[0];
            acc = fmaf(sB[i*128+0], w1a[0], acc);
            acc = fmaf(sB[i*128+1], w1b[0], acc);
            acc = fmaf(sB[i*128+2], w1c[0], acc);
            sA[i*128 + k64] = fmaxf(acc, 0.f);
        }
        cpa_wait<1>();        // F2 staged (F3 may still be in flight)
        __syncthreads();

        // layer2: 64 -> 128, ILP-4
        float acc2[4];
        #pragma unroll
        for (int j = 0; j < 4; j++) acc2[j] = bf2[0];
        #pragma unroll 4
        for (int kk = 0; kk < 64; kk++) {
            float w = sF2[kk*128 + c];
            #pragma unroll
            for (int j = 0; j < 4; j++)
                acc2[j] = fmaf(sA[(g3c*4 + j)*128 + kk], w, acc2[j]);
        }
        #pragma unroll
        for (int j = 0; j < 4; j++) sB[(g3c*4 + j)*128 + c] = fmaxf(acc2[j], 0.f);
        cpa_wait<0>();        // F3 staged
        __syncthreads();

        // layer3: 128 -> 128 single pass, ILP-4
        float acc3[4];
        #pragma unroll
        for (int j = 0; j < 4; j++) acc3[j] = bf3[0];
        #pragma unroll 4
        for (int kk = 0; kk < 128; kk++) {
            float w = sF3[kk*128 + c];
            #pragma unroll
            for (int j = 0; j < 4; j++)
                acc3[j] = fmaf(sB[(g3c*4 + j)*128 + kk], w, acc3[j]);
        }
        float* F0 = g_Fbuf[0] + base*128;
        #pragma unroll
        for (int j = 0; j < 4; j++)
            F0[(g3c*4 + j)*128 + c] = fmaxf(acc3[j], 0.f);
    }
    grid_bar();

    // ================= 3 timesteps =================
    int cur = 0;
    #pragma unroll
    for (int s = 0; s < 3; s++) {
        // stage this step's weights in the background (first-use order)
        cpa(sG1, gW1 + s*8192, 8192);
        cpa(sG2, gW2 + s*2048, 2048);
        cpa_commit();                               // group G
        if (s < 2) {
            cpa(sF2, fW2 + (s+1)*8192, 8192);  cpa_commit();   // group F2
            cpa(sF3, fW3 + (s+1)*16384, 16384); cpa_commit();  // group F3
        }
        if (t < 96) sG3[t] = gW3[s*96 + t];

        // phase A: channelwise max over neighbors, 8 loads in flight
        const float* Fn = g_Fbuf[cur] + n*MM*128;
        #pragma unroll
        for (int j = 0; j < 4; j++) {
            int i  = g3c*4 + j;
            int dg = sD[i];
            const unsigned short* Ni = sN + i*MAXD;
            float m = 0.f;
            for (int d = 0; d < dg; d += 8) {
                float v0 = Fn[Ni[d+0]*128 + c], v1 = Fn[Ni[d+1]*128 + c];
                float v2 = Fn[Ni[d+2]*128 + c], v3 = Fn[Ni[d+3]*128 + c];
                float v4 = Fn[Ni[d+4]*128 + c], v5 = Fn[Ni[d+5]*128 + c];
                float v6 = Fn[Ni[d+6]*128 + c], v7 = Fn[Ni[d+7]*128 + c];
                float m01 = fmaxf(v0, v1), m23 = fmaxf(v2, v3);
                float m45 = fmaxf(v4, v5), m67 = fmaxf(v6, v7);
                m = fmaxf(m, fmaxf(fmaxf(m01, m23), fmaxf(m45, m67)));
            }
            sA[i*128 + c] = m;
        }
        if (s < 2) cpa_wait<2>(); else cpa_wait<0>();   // g-weights staged
        __syncthreads();

        // phase B: g layer1 (128 -> 64), ILP-2, weights in smem
        {
            float a0 = bg1[s], a1 = bg1[s];
            const float* A0 = sA + (h6*2)*128, * A1 = A0 + 128;
            #pragma unroll 8
            for (int d = 0; d < 128; d++) {
                float w = sG1[d*64 + k64];
                a0 = fmaf(A0[d], w, a0);
                a1 = fmaf(A1[d], w, a1);
            }
            sB[(h6*2    )*128 + k64] = fmaxf(a0, 0.f);
            sB[(h6*2 + 1)*128 + k64] = fmaxf(a1, 0.f);
        }
        __syncthreads();

        // phase C: g layer2 (64 -> 32), weights in smem
        {
            int k2 = t & 31, i12 = t >> 5;
            float a = bg2[s];
            #pragma unroll 8
            for (int d = 0; d < 64; d++)
                a = fmaf(sB[i12*128 + d], sG2[d*32 + k2], a);
            sA[i12*128 + k2] = fmaxf(a, 0.f);
        }
        __syncthreads();

        // phase D: g layer3 (32 -> 3) + relu + residual (state in regs)
        if (t < BN*3) {
            int i = t / 3, d = t % 3;
            float acc = bg3s[s];
            #pragma unroll
            for (int k3 = 0; k3 < 32; k3++)
                acc = fmaf(sA[i*128 + k3], sG3[k3*3 + d], acc);
            float ns = stv + fmaxf(acc, 0.f);
            stv = ns;
            if (s == 2) state[base*3 + t] = ns;    // final output, once
            else        sB[i*128 + d] = ns;        // feed next f phase
        }
        __syncthreads();

        if (s < 2) {
            // ---- MLP_f for step s+1 ----
            #pragma unroll
            for (int j = 0; j < 2; j++) {
                int i = h6*2 + j;
                float acc = bf1[s+1];
                acc = fmaf(sB[i*128+0], w1a[s+1], acc);
                acc = fmaf(sB[i*128+1], w1b[s+1], acc);
                acc = fmaf(sB[i*128+2], w1c[s+1], acc);
                sA[i*128 + k64] = fmaxf(acc, 0.f);
            }
            cpa_wait<1>();        // F2 staged
            __syncthreads();

            float acc2[4];
            #pragma unroll
            for (int j = 0; j < 4; j++) acc2[j] = bf2[s+1];
            #pragma unroll 4
            for (int kk = 0; kk < 64; kk++) {
                float w = sF2[kk*128 + c];
                #pragma unroll
                for (int j = 0; j < 4; j++)
                    acc2[j] = fmaf(sA[(g3c*4 + j)*128 + kk], w, acc2[j]);
            }
            #pragma unroll
            for (int j = 0; j < 4; j++)
                sB[(g3c*4 + j)*128 + c] = fmaxf(acc2[j], 0.f);
            cpa_wait<0>();        // F3 staged
            __syncthreads();

            float acc3[4];
            #pragma unroll
            for (int j = 0; j < 4; j++) acc3[j] = bf3[s+1];
            #pragma unroll 4
            for (int kk = 0; kk < 128; kk++) {
                float w = sF3[kk*128 + c];
                #pragma unroll
                for (int j = 0; j < 4; j++)
                    acc3[j] = fmaf(sB[(g3c*4 + j)*128 + kk], w, acc3[j]);
            }
            float* Fo = g_Fbuf[cur ^ 1] + base*128;
            #pragma unroll
            for (int j = 0; j < 4; j++)
                Fo[(g3c*4 + j)*128 + c] = fmaxf(acc3[j], 0.f);

            grid_bar();
            cur ^= 1;
        }
    }
}

// ---------------------------------------------------------------------------
extern "C" void kernel_launch(void* const* d_in, const int* in_sizes, int n_in,
                              void* d_out, int out_size) {
    const float* x   = (const float*)d_in[0];
    const float* fW1 = (const float*)d_in[7];
    const float* fb1 = (const float*)d_in[8];
    const float* fW2 = (const float*)d_in[9];
    const float* fb2 = (const float*)d_in[10];
    const float* fW3 = (const float*)d_in[11];
    const float* fb3 = (const float*)d_in[12];
    const float* gW1 = (const float*)d_in[13];
    const float* gb1 = (const float*)d_in[14];
    const float* gW2 = (const float*)d_in[15];
    const float* gb2 = (const float*)d_in[16];
    const float* gW3 = (const float*)d_in[17];
    const float* gb3 = (const float*)d_in[18];
    float* state = (float*)d_out;

    cudaFuncSetAttribute(pointgnn_persistent,
                         cudaFuncAttributeMaxDynamicSharedMemorySize, SMEM_BYTES);

    pointgnn_persistent<<<GRID, TPB, SMEM_BYTES>>>(x, state,
        fW1, fb1, fW2, fb2, fW3, fb3,
        gW1, gb1, gW2, gb2, gW3, gb3);
}